// round 13
// baseline (speedup 1.0000x reference)
#include <cuda_runtime.h>
#include <cuda_bf16.h>
#include <stdint.h>

// out[B=1024, W=201000] f32 one-hot triple scatter over zeros.
// Inputs: z f32 (unused), hID i32[1024], rID i32[1024], tID i32[1024].
//
// Hybrid concurrent fill:
//   CE branch : memset rows [0,512) + 4B memset of g_flag (ordered after).
//   SM branch : fused fill+scatter of rows [512,1024) (disjoint, concurrent),
//               plus one dedicated block that polls g_flag and then scatters
//               region A's ones from inside the running kernel (no CE->kernel
//               node-transition latency, which measures ~7.5us fixed).

#define ENTITIES_N  100000
#define RELATIONS_N 1000
#define WIDTH       201000
#define BATCH       1024
#define ROWS_A      512
#define ROWS_B      512
#define B_V8        12864000u            // 512*201000/8
#define W8          25125u               // v8 chunks per row
#define THREADS     256
#define V8_PER_THR  5
#define V8_PER_BLK  (THREADS * V8_PER_THR)        // 1280
#define FILL_BLOCKS (B_V8 / V8_PER_BLK)           // 10050 exact
#define GRID        (FILL_BLOCKS + 1)             // +1 poller/scatter-A block

__device__ int g_flag;   // zero-initialized; set by CE, reset by poller

__global__ void __launch_bounds__(THREADS) hybrid_fill(
    const int* __restrict__ hID,
    const int* __restrict__ rID,
    const int* __restrict__ tID,
    float* __restrict__ out)
{
    float* outB = out + (size_t)ROWS_A * WIDTH;

    if (blockIdx.x < FILL_BLOCKS) {
        // ---- Region B fill: 5 x st.global.v8 per thread ----
        const unsigned base = blockIdx.x * (unsigned)V8_PER_BLK + threadIdx.x;
#pragma unroll
        for (int k = 0; k < V8_PER_THR; k++) {
            float* addr = outB + (size_t)(base + k * THREADS) * 8;
            asm volatile(
                "st.global.v8.f32 [%0], {%1,%1,%1,%1,%1,%1,%1,%1};"
                :: "l"(addr), "f"(0.0f) : "memory");
        }

        // ---- Region B hot elements owned by this thread ----
        const unsigned rowA = base / W8;
        const unsigned rowB = (base + (V8_PER_THR - 1) * THREADS) / W8;
#pragma unroll
        for (int which = 0; which < 2; which++) {
            const unsigned rrel = which ? rowB : rowA;
            if (which && rowB == rowA) break;
            const unsigned grow = rrel + ROWS_A;
            unsigned q[3];
            q[0] = rrel * (unsigned)WIDTH + (unsigned)__ldg(&hID[grow]);
            q[1] = rrel * (unsigned)WIDTH + (unsigned)(ENTITIES_N + __ldg(&rID[grow]));
            q[2] = rrel * (unsigned)WIDTH + (unsigned)(ENTITIES_N + RELATIONS_N +
                                                       __ldg(&tID[grow]));
#pragma unroll
            for (int j = 0; j < 3; j++) {
                const unsigned chunk = q[j] >> 3;
                const unsigned d = chunk - base;       // unsigned wrap ok
                if (d < (unsigned)V8_PER_BLK && (d & (THREADS - 1)) == 0u)
                    outB[q[j]] = 1.0f;                 // same-thread order
            }
        }
    } else {
        // ---- Poller block: wait for CE memset of region A, then scatter ----
        volatile int* flag = &g_flag;
        while (*flag == 0) { }
        __threadfence();   // acquire: CE zeros visible/ordered before our 1.0s

        // 512 rows * 3 = 1536 stores over 256 threads (6 each, independent).
        for (unsigned t = threadIdx.x; t < ROWS_A * 3u; t += THREADS) {
            const unsigned row = t / 3u;
            const unsigned j   = t % 3u;
            const int* src = (j == 0) ? hID : (j == 1) ? rID : tID;
            const unsigned off = (j == 0) ? 0u
                               : (j == 1) ? (unsigned)ENTITIES_N
                                          : (unsigned)(ENTITIES_N + RELATIONS_N);
            out[(size_t)row * WIDTH + off + (unsigned)__ldg(&src[row])] = 1.0f;
        }
        __syncthreads();
        if (threadIdx.x == 0) g_flag = 0;   // reset for next graph replay
    }
}

extern "C" void kernel_launch(void* const* d_in, const int* in_sizes, int n_in,
                              void* d_out, int out_size) {
    const int* hID = (const int*)d_in[1];
    const int* rID = (const int*)d_in[2];
    const int* tID = (const int*)d_in[3];
    float* out = (float*)d_out;

    static cudaStream_t side = nullptr;
    static cudaEvent_t evFork = nullptr, evJoin = nullptr;
    static void* flag_addr = nullptr;
    if (!side) {
        cudaStreamCreateWithFlags(&side, cudaStreamNonBlocking);
        cudaEventCreateWithFlags(&evFork, cudaEventDisableTiming);
        cudaEventCreateWithFlags(&evJoin, cudaEventDisableTiming);
        cudaGetSymbolAddress(&flag_addr, g_flag);
    }

    // Fork CE branch: zero region A, then set the flag (stream-ordered).
    cudaEventRecord(evFork, 0);
    cudaStreamWaitEvent(side, evFork, 0);
    cudaMemsetAsync(out, 0, (size_t)ROWS_A * WIDTH * sizeof(float), side);
    cudaMemsetAsync(flag_addr, 1, sizeof(int), side);   // nonzero pattern
    cudaEventRecord(evJoin, side);

    // SM branch: concurrent fill of region B + in-kernel region-A scatter.
    hybrid_fill<<<GRID, THREADS>>>(hID, rID, tID, out);

    // Join CE branch into the main stream for completion semantics.
    cudaStreamWaitEvent(0, evJoin, 0);
}